// round 16
// baseline (speedup 1.0000x reference)
#include <cuda_runtime.h>
#include <cuda_fp16.h>
#include <cstdint>

#define BB 16
#define DD 256
#define TT 2048
#define KK 8192
#define NN (BB*TT)          /* 32768 tokens  */
#define NQ (BB*DD*TT)       /* 8388608 elems */

typedef unsigned int uint;

// ---------------------------------------------------------------------------
// Scratch (static __device__ arrays: allocation-free per harness rules)
__device__ __align__(128) uint g_zh2[DD * NN];      // 32MB: z fp16 dup (h,h), [d][token]
__device__ __align__(128) uint g_eh[DD * KK / 2];   //  4MB: emb fp16 pairs, [d][kpair]
__device__ float g_embT[DD*KK];    // emb transposed [D][K] (for k_quant + prepB)
__device__ float g_enorm[KK];      // ||e_k||^2 (exact fp32)
__device__ float g_s1[NN];         // ||z_n||^2 (sequential-d fp32)
__device__ float g_f2[NN];         // 2*sz_n*se
__device__ uint  g_seU;            // max|emb| as float bits
__device__ int   g_idx[NN];        // argmin per token
__device__ float g_partial[1024];  // loss partials

// order-preserving float<->uint (monotonic; atomicMin-able)
__device__ __forceinline__ uint encf(float f) {
    uint b = __float_as_uint(f);
    return (b & 0x80000000u) ? ~b : (b | 0x80000000u);
}
__device__ __forceinline__ float decf(uint u) {
    return (u & 0x80000000u) ? __uint_as_float(u & 0x7fffffffu)
                             : __uint_as_float(~u);
}
__device__ __forceinline__ uint s2u(const void* p) {
    uint a;
    asm("{ .reg .u64 t; cvta.to.shared.u64 t, %1; cvt.u32.u64 %0, t; }"
        : "=r"(a) : "l"(p));
    return a;
}
__device__ __forceinline__ void cpa16(uint dst, const void* src) {
    asm volatile("cp.async.cg.shared.global [%0], [%1], 16;"
                 :: "r"(dst), "l"(src) : "memory");
}
__device__ __forceinline__ void cpcommit() {
    asm volatile("cp.async.commit_group;" ::: "memory");
}

// ---------------------------------------------------------------------------
// emb [K,D] -> embT [D,K]
__global__ void k_transpose(const float* __restrict__ emb) {
    __shared__ float tile[32][33];
    int k0 = blockIdx.x * 32, d0 = blockIdx.y * 32;
    int tx = threadIdx.x, ty = threadIdx.y;
    #pragma unroll
    for (int i = 0; i < 32; i += 8)
        tile[ty + i][tx] = emb[(size_t)(k0 + ty + i) * DD + d0 + tx];
    __syncthreads();
    #pragma unroll
    for (int i = 0; i < 32; i += 8)
        g_embT[(size_t)(d0 + ty + i) * KK + k0 + tx] = tile[tx][ty + i];
}

// per-code squared norms (UNCHANGED from the rel_err=0 kernel)
__global__ void k_norms(const float* __restrict__ emb) {
    int r = blockIdx.x * 8 + (threadIdx.x >> 5);
    int lane = threadIdx.x & 31;
    float s = 0.f;
    for (int i = lane; i < DD; i += 32) {
        float v = emb[(size_t)r * DD + i];
        s += v * v;
    }
    #pragma unroll
    for (int o = 16; o > 0; o >>= 1) s += __shfl_xor_sync(0xffffffffu, s, o);
    if (lane == 0) g_enorm[r] = s;
}

__global__ void k_zero() { g_seU = 0u; }

// global max|emb| (max is order-invariant -> deterministic)
__global__ void k_semax(const float* __restrict__ emb) {
    __shared__ float red[256];
    float m = 0.f;
    for (int i = blockIdx.x * 256 + threadIdx.x; i < KK * DD; i += 256 * 256)
        m = fmaxf(m, fabsf(emb[i]));
    red[threadIdx.x] = m;
    __syncthreads();
    #pragma unroll
    for (int o = 128; o > 0; o >>= 1) {
        if (threadIdx.x < o) red[threadIdx.x] = fmaxf(red[threadIdx.x], red[threadIdx.x + o]);
        __syncthreads();
    }
    if (threadIdx.x == 0) atomicMax(&g_seU, __float_as_uint(red[0]));
}

// z -> scaled fp16 dup (h,h) [d][token]; ||z||^2 sequential-d fp32; f2 scale
__global__ void k_prepA(const float* __restrict__ z) {
    int n = blockIdx.x * 128 + threadIdx.x;
    const float* zp = z + (size_t)(n >> 11) * DD * TT + (n & (TT - 1));
    float se = __uint_as_float(g_seU);
    float s1 = 0.f, mx = 0.f;
    for (int d0 = 0; d0 < DD; d0 += 8) {
        float v[8];
        #pragma unroll
        for (int u = 0; u < 8; u++) v[u] = zp[(size_t)(d0 + u) * TT];
        #pragma unroll
        for (int u = 0; u < 8; u++) s1 += v[u] * v[u];
        #pragma unroll
        for (int u = 0; u < 8; u++) mx = fmaxf(mx, fabsf(v[u]));
    }
    float sz = fmaxf(mx, 1e-30f);
    float qs = 1.0f / sz;
    for (int d = 0; d < DD; d++) {
        __half h = __float2half_rn(zp[(size_t)d * TT] * qs);
        uint hb = (uint)(*(unsigned short*)&h);
        g_zh2[(size_t)d * NN + n] = hb | (hb << 16);
    }
    g_s1[n] = s1;
    g_f2[n] = 2.0f * sz * se;
}

// emb -> scaled fp16 pairs [d][kpair] (reads embT: coalesced)
__global__ void k_prepB(const float* /*emb*/) {
    int jp = blockIdx.x * 128 + threadIdx.x;       // 0..4095 code pairs
    float qs = 1.0f / __uint_as_float(g_seU);
    for (int d = 0; d < DD; d++) {
        float e0 = g_embT[(size_t)d * KK + 2 * jp];
        float e1 = g_embT[(size_t)d * KK + 2 * jp + 1];
        __half2 h = __floats2half2_rn(e0 * qs, e1 * qs);
        g_eh[(size_t)d * (KK / 2) + jp] = *(uint*)&h;
    }
}

// ---------------------------------------------------------------------------
// HFMA2 pass-1: 32 tokens/block x all 8192 codes, ct tile = 256 codes.
// A resident, B cp.async 2-buffer ring of 64-d stages. occupancy 2.
// Two-phase candidate epilogue + exact fp32 rescue.
#define CAP 32
#define MARGIN 2.5e-4f
#define NSTG 128                     /* 32 ct x 4 d-stages of 64 */

#define SM_A    0                    /* [256 d][32 tok] dup uints, 32KB */
#define SM_B    32768                /* 2 x [64 d][128 pair] uints, 64KB */
#define SM_BEST 98304
#define SM_CNT  98432
#define SM_CAND 98560                /* 32 x CAP ints, 4KB */
#define SM_RD   102656
#define SM_RI   103680
#define SMEMSZ  104704

__global__ __launch_bounds__(256, 2)
void k_argmin_h2(const float* __restrict__ z, const float* __restrict__ emb,
                 float* __restrict__ idxOutF, int writeIdx) {
    extern __shared__ char sm[];
    uint sb = s2u(sm);
    int tid = threadIdx.x;
    int ty = tid >> 5, tx = tid & 31;      // warp = 4 tokens; lane = 4 pairs (8 codes)
    int tile = blockIdx.x;
    int t0 = tile * 32;

    uint* sBest = (uint*)(sm + SM_BEST);
    int*  sCnt  = (int*)(sm + SM_CNT);
    int*  sCand = (int*)(sm + SM_CAND);

    if (tid < 32) { sBest[tid] = encf(3.4e38f); sCnt[tid] = 0; }

    float f2r[4];
    #pragma unroll
    for (int i = 0; i < 4; i++) f2r[i] = g_f2[t0 + ty * 4 + i];

    // A resident load: row d = tid, 32 dup-uints (=128B)
    {
        const char* src = (const char*)(g_zh2 + (size_t)tid * NN + t0);
        uint dst = sb + SM_A + tid * 128;
        #pragma unroll
        for (int j = 0; j < 8; j++) cpa16(dst + j * 16, src + j * 16);
    }
    // B stage loader: stage S -> ct=S>>2, dbase=(S&3)*64, buf=S&1
    // stage = [64 d][128 pairs] = 32KB; thread loads 128B of row rr
    auto loadB = [&](int S) {
        int ct = S >> 2, dbase = (S & 3) * 64, buf = S & 1;
        int rr = tid >> 2, sg = (tid & 3) * 32;    // 32-uint segment
        const char* src = (const char*)(g_eh + (size_t)(dbase + rr) * (KK / 2) + ct * 128 + sg);
        uint dst = sb + SM_B + buf * 32768 + rr * 512 + sg * 4;
        #pragma unroll
        for (int j = 0; j < 8; j++) cpa16(dst + j * 16, src + j * 16);
    };
    loadB(0); cpcommit();                  // group: A + stage0

    __half2 acc2[4][4];
    float   accf[4][8];
    #pragma unroll
    for (int i = 0; i < 4; i++) {
        #pragma unroll
        for (int p = 0; p < 4; p++) acc2[i][p] = __float2half2_rn(0.f);
        #pragma unroll
        for (int j = 0; j < 8; j++) accf[i][j] = 0.f;
    }

    const uint* smu = (const uint*)sm;

    for (int S = 0; S < NSTG; S++) {
        asm volatile("cp.async.wait_group 0;" ::: "memory");
        __syncthreads();                   // stage S visible; S-1 compute done
        if (S + 1 < NSTG) { loadB(S + 1); cpcommit(); }

        const uint* Arow = smu + ((SM_A + (S & 3) * 64 * 128) >> 2) + ty * 4;
        const uint* Brow = smu + ((SM_B + (S & 1) * 32768) >> 2) + tx * 4;
        #pragma unroll 4
        for (int dd = 0; dd < 64; dd++) {
            uint4 av = *(const uint4*)(Arow + dd * 32);    // 4 tokens (dup h2), bcast
            uint4 bv = *(const uint4*)(Brow + dd * 128);   // 4 pairs = 8 codes
            __half2 b2[4];
            b2[0] = *(__half2*)&bv.x; b2[1] = *(__half2*)&bv.y;
            b2[2] = *(__half2*)&bv.z; b2[3] = *(__half2*)&bv.w;
            #pragma unroll
            for (int i = 0; i < 4; i++) {
                __half2 ai = *(__half2*)(((uint*)&av) + i);
                #pragma unroll
                for (int p = 0; p < 4; p++)
                    acc2[i][p] = __hfma2(ai, b2[p], acc2[i][p]);
            }
        }
        // phase promote (every 64 d): fp16 -> fp32
        #pragma unroll
        for (int i = 0; i < 4; i++)
            #pragma unroll
            for (int p = 0; p < 4; p++) {
                accf[i][2 * p]     += __low2float(acc2[i][p]);
                accf[i][2 * p + 1] += __high2float(acc2[i][p]);
                acc2[i][p] = __float2half2_rn(0.f);
            }

        if ((S & 3) == 3) {                // ct complete (256 codes): epilogue
            int ct = S >> 2;
            int kbase = ct * 256 + tx * 8;
            float enj[8];
            *(float4*)(enj)     = *(const float4*)&g_enorm[kbase];
            *(float4*)(enj + 4) = *(const float4*)&g_enorm[kbase + 4];
            // pass 1: per-token running best (monotone shared atomicMin)
            #pragma unroll
            for (int i = 0; i < 4; i++) {
                int tok = ty * 4 + i;
                float lmin = 3.4e38f;
                #pragma unroll
                for (int j = 0; j < 8; j++) {
                    float da = fmaf(-f2r[i], accf[i][j], enj[j]);
                    if (da < lmin) lmin = da;
                }
                if (lmin < decf(sBest[tok])) atomicMin(&sBest[tok], encf(lmin));
            }
            __syncthreads();               // bests visible
            // pass 2: append within MARGIN of global-running best
            #pragma unroll
            for (int i = 0; i < 4; i++) {
                int tok = ty * 4 + i;
                float thr = decf(sBest[tok]) + MARGIN;
                #pragma unroll
                for (int j = 0; j < 8; j++) {
                    float da = fmaf(-f2r[i], accf[i][j], enj[j]);
                    if (da < thr) {
                        int pos = atomicAdd(&sCnt[tok], 1);
                        if (pos < CAP) sCand[tok * CAP + pos] = kbase + j;
                    }
                    accf[i][j] = 0.f;
                }
            }
            // next stage-top sync orders pass2 reads vs next ct's pass1 writes
        }
    }
    __syncthreads();

    // -------- exact fp32 rescue (reference rounding), 8 threads per token
    float* rD = (float*)(sm + SM_RD);
    int*   rI = (int*)(sm + SM_RI);
    {
        int r = tid & 31, part = tid >> 5;
        int n = t0 + r;
        const float* zp = z + (size_t)(n >> 11) * DD * TT + (n & (TT - 1));
        float s1 = g_s1[n];
        int cnt = sCnt[r];
        float bestd = 3.4e38f; int besti = 0x7fffffff;
        if (cnt <= CAP) {
            for (int q = part; q < cnt; q += 8) {
                int k = sCand[r * CAP + q];
                const float* ep = emb + (size_t)k * DD;
                float dot = 0.f;
                #pragma unroll 8
                for (int d = 0; d < DD; d++) dot += zp[(size_t)d * TT] * ep[d];
                float c = s1 + g_enorm[k];
                float dist = c - 2.0f * dot;     // == fl(c - 2*dot), *2 exact
                if (dist < bestd || (dist == bestd && k < besti)) { bestd = dist; besti = k; }
            }
        } else {                                  // overflow: exact full scan
            for (int k = part; k < KK; k += 8) {
                const float* ep = emb + (size_t)k * DD;
                float dot = 0.f;
                #pragma unroll 8
                for (int d = 0; d < DD; d++) dot += zp[(size_t)d * TT] * ep[d];
                float c = s1 + g_enorm[k];
                float dist = c - 2.0f * dot;
                if (dist < bestd || (dist == bestd && k < besti)) { bestd = dist; besti = k; }
            }
        }
        rD[tid] = bestd; rI[tid] = besti;
    }
    __syncthreads();
    if (tid < 32) {
        float best = rD[tid]; int besti = rI[tid];
        #pragma unroll
        for (int p = 1; p < 8; p++) {
            float d = rD[p * 32 + tid]; int ii = rI[p * 32 + tid];
            if (d < best || (d == best && ii < besti)) { best = d; besti = ii; }
        }
        int n = t0 + tid;
        g_idx[n] = besti;
        if (writeIdx) idxOutF[n] = (float)besti;
    }
}

// ---------------------------------------------------------------------------
// Gather + straight-through output + loss partials (deterministic order)
__global__ void k_quant(const float* __restrict__ z, float* __restrict__ out) {
    __shared__ float red[256];
    size_t base = (size_t)blockIdx.x * 8192;
    float ls = 0.f;
    #pragma unroll 4
    for (int j = 0; j < 32; j++) {
        size_t i = base + threadIdx.x + (size_t)j * 256;
        int t = (int)(i & (TT - 1));
        int d = (int)((i >> 11) & (DD - 1));
        int b = (int)(i >> 19);
        int n = b * TT + t;
        float zv = z[i];
        float q  = g_embT[(size_t)d * KK + g_idx[n]];
        float diff = q - zv;
        out[i] = zv + diff;                // z + (q - z): reference rounding
        ls += diff * diff;
    }
    red[threadIdx.x] = ls;
    __syncthreads();
    #pragma unroll
    for (int o = 128; o > 0; o >>= 1) {
        if (threadIdx.x < o) red[threadIdx.x] += red[threadIdx.x + o];
        __syncthreads();
    }
    if (threadIdx.x == 0) g_partial[blockIdx.x] = red[0];
}

__global__ void k_final(float* out_loss, int doWrite) {
    __shared__ float red[256];
    float s = 0.f;
    #pragma unroll
    for (int j = 0; j < 4; j++) s += g_partial[threadIdx.x + j * 256];
    red[threadIdx.x] = s;
    __syncthreads();
    #pragma unroll
    for (int o = 128; o > 0; o >>= 1) {
        if (threadIdx.x < o) red[threadIdx.x] += red[threadIdx.x + o];
        __syncthreads();
    }
    if (threadIdx.x == 0 && doWrite)
        out_loss[0] = 1.25f * (red[0] / (float)NQ);
}

// ---------------------------------------------------------------------------
extern "C" void kernel_launch(void* const* d_in, const int* in_sizes, int n_in,
                              void* d_out, int out_size) {
    const float* z   = (const float*)d_in[0];
    const float* emb = (const float*)d_in[1];
    if (n_in >= 2 && in_sizes[0] == KK * DD && in_sizes[1] == NQ) {
        const float* tmp = z; z = emb; emb = tmp;   // defensive input-order swap
    }
    float* out = (float*)d_out;
    int writeTail = (out_size >= NQ + 1 + NN) ? 1 : 0;

    static int attrSet = 0;
    if (!attrSet) {
        cudaFuncSetAttribute(k_argmin_h2,
                             cudaFuncAttributeMaxDynamicSharedMemorySize, SMEMSZ);
        attrSet = 1;
    }

    k_transpose<<<dim3(KK / 32, DD / 32), dim3(32, 8)>>>(emb);
    k_norms<<<KK / 8, 256>>>(emb);
    k_zero<<<1, 1>>>();
    k_semax<<<256, 256>>>(emb);
    k_prepA<<<NN / 128, 128>>>(z);
    k_prepB<<<KK / 256, 128>>>(emb);
    k_argmin_h2<<<NN / 32, 256, SMEMSZ>>>(z, emb, out + NQ + 1, writeTail);
    k_quant<<<1024, 256>>>(z, out);
    k_final<<<1, 256>>>(out + NQ, writeTail);
}